// round 3
// baseline (speedup 1.0000x reference)
#include <cuda_runtime.h>
#include <math.h>

#define HD 4096
#define LD 4096
#define VD 128000

// ---------------- scratch (device globals; no allocations) ----------------
__device__ float g_logits[LD];
__device__ float g_lse_attn;
__device__ float g_attn_applied[HD];
__device__ float g_lstm_in[HD];
__device__ float g_gates[4 * HD];
__device__ float g_hnew[HD];
__device__ float g_word[VD];
__device__ float g_pmax[VD / 256];
__device__ float g_psum[VD / 256];
__device__ float g_lse_word;

// ---------------- generic dual mat-vec: out[r] = A[r,:]·v1 + B[r,:]·v2 + b1[r] + b2[r]
// warp-per-row, float4 loads, unrolled for MLP
__global__ void matvec2_kernel(const float* __restrict__ A, int strideA,
                               const float* __restrict__ v1, int n1,
                               const float* __restrict__ B, int strideB,
                               const float* __restrict__ v2, int n2,
                               const float* __restrict__ bias1,
                               const float* __restrict__ bias2,
                               float* __restrict__ out, int rows)
{
    int warp = (blockIdx.x * blockDim.x + threadIdx.x) >> 5;
    int lane = threadIdx.x & 31;
    if (warp >= rows) return;

    float sum = 0.0f;
    {
        const float4* a  = (const float4*)(A + (size_t)warp * strideA);
        const float4* vv = (const float4*)v1;
        int n4 = n1 >> 2;
        #pragma unroll 8
        for (int i = lane; i < n4; i += 32) {
            float4 av = a[i], bv = vv[i];
            sum += av.x * bv.x + av.y * bv.y + av.z * bv.z + av.w * bv.w;
        }
    }
    if (B) {
        const float4* b  = (const float4*)(B + (size_t)warp * strideB);
        const float4* vv = (const float4*)v2;
        int n4 = n2 >> 2;
        #pragma unroll 8
        for (int i = lane; i < n4; i += 32) {
            float4 av = b[i], bv = vv[i];
            sum += av.x * bv.x + av.y * bv.y + av.z * bv.z + av.w * bv.w;
        }
    }
    #pragma unroll
    for (int o = 16; o; o >>= 1) sum += __shfl_xor_sync(0xFFFFFFFFu, sum, o);
    if (lane == 0) {
        float b = bias1 ? bias1[warp] : 0.0f;
        if (bias2) b += bias2[warp];
        out[warp] = sum + b;
    }
}

// ---------------- block reduction helpers ----------------
__device__ __forceinline__ float block_reduce_max(float v, float* sm) {
    int lane = threadIdx.x & 31, wid = threadIdx.x >> 5;
    int nwarp = blockDim.x >> 5;
    #pragma unroll
    for (int o = 16; o; o >>= 1) v = fmaxf(v, __shfl_xor_sync(0xFFFFFFFFu, v, o));
    if (lane == 0) sm[wid] = v;
    __syncthreads();
    float r = (threadIdx.x < nwarp) ? sm[threadIdx.x] : -1e30f;
    if (wid == 0) {
        #pragma unroll
        for (int o = 16; o; o >>= 1) r = fmaxf(r, __shfl_xor_sync(0xFFFFFFFFu, r, o));
        if (lane == 0) sm[0] = r;
    }
    __syncthreads();
    float m = sm[0];
    __syncthreads();
    return m;
}

__device__ __forceinline__ float block_reduce_sum(float v, float* sm) {
    int lane = threadIdx.x & 31, wid = threadIdx.x >> 5;
    int nwarp = blockDim.x >> 5;
    #pragma unroll
    for (int o = 16; o; o >>= 1) v += __shfl_xor_sync(0xFFFFFFFFu, v, o);
    if (lane == 0) sm[wid] = v;
    __syncthreads();
    float r = (threadIdx.x < nwarp) ? sm[threadIdx.x] : 0.0f;
    if (wid == 0) {
        #pragma unroll
        for (int o = 16; o; o >>= 1) r += __shfl_xor_sync(0xFFFFFFFFu, r, o);
        if (lane == 0) sm[0] = r;
    }
    __syncthreads();
    float s = sm[0];
    __syncthreads();
    return s;
}

// ---------------- attention logsumexp (L=4096, one block) + zero attn_applied
__global__ void attn_lse_kernel() {
    __shared__ float sm[32];
    int t = threadIdx.x;
    float m = -1e30f;
    for (int i = t; i < LD; i += blockDim.x) m = fmaxf(m, g_logits[i]);
    float M = block_reduce_max(m, sm);
    float s = 0.0f;
    for (int i = t; i < LD; i += blockDim.x) s += expf(g_logits[i] - M);
    float S = block_reduce_sum(s, sm);
    if (t == 0) g_lse_attn = M + logf(S);
    for (int i = t; i < HD; i += blockDim.x) g_attn_applied[i] = 0.0f;
}

// ---------------- attn_applied[c] = sum_l (logit[l]-lse) * enc[l,c]
// grid (HD/256, RSLICES), threads 256; atomicAdd of per-slice partials
__global__ void attn_applied_kernel(const float* __restrict__ enc) {
    int col = blockIdx.x * blockDim.x + threadIdx.x;
    int per = LD / gridDim.y;
    int l0 = blockIdx.y * per;
    float lse = g_lse_attn;
    float acc = 0.0f;
    #pragma unroll 4
    for (int l = l0; l < l0 + per; ++l)
        acc += (g_logits[l] - lse) * enc[(size_t)l * HD + col];
    atomicAdd(&g_attn_applied[col], acc);
}

// ---------------- LSTM cell elementwise ----------------
__global__ void lstm_kernel(const float* __restrict__ c0) {
    int i = blockIdx.x * blockDim.x + threadIdx.x;
    if (i >= HD) return;
    float ig = g_gates[i];
    float fg = g_gates[i + HD];
    float gg = g_gates[i + 2 * HD];
    float og = g_gates[i + 3 * HD];
    float si = 1.0f / (1.0f + expf(-ig));
    float sf = 1.0f / (1.0f + expf(-fg));
    float so = 1.0f / (1.0f + expf(-og));
    float cn = sf * c0[i] + si * tanhf(gg);
    g_hnew[i] = so * tanhf(cn);
}

// ---------------- vocab logsumexp: stage A (per-block partials) ----------------
__global__ void word_lse_partial_kernel() {
    __shared__ float sm[32];
    int idx = blockIdx.x * blockDim.x + threadIdx.x;
    float x = g_word[idx];                 // V divisible by 256
    float M = block_reduce_max(x, sm);
    float S = block_reduce_sum(expf(x - M), sm);
    if (threadIdx.x == 0) { g_pmax[blockIdx.x] = M; g_psum[blockIdx.x] = S; }
}

// ---------------- vocab logsumexp: stage B (combine) ----------------
__global__ void word_lse_final_kernel(int nparts) {
    __shared__ float sm[32];
    int t = threadIdx.x;
    float m = (t < nparts) ? g_pmax[t] : -1e30f;
    float M = block_reduce_max(m, sm);
    float s = (t < nparts) ? g_psum[t] * expf(g_pmax[t] - M) : 0.0f;
    float S = block_reduce_sum(s, sm);
    if (t == 0) g_lse_word = M + logf(S);
}

// ---------------- final: out = word - lse ----------------
__global__ void final_kernel(float* __restrict__ out) {
    int i = blockIdx.x * blockDim.x + threadIdx.x;
    if (i < VD) out[i] = g_word[i] - g_lse_word;
}

// ======================================================================
extern "C" void kernel_launch(void* const* d_in, const int* in_sizes, int n_in,
                              void* d_out, int out_size) {
    const float* enc    = (const float*)d_in[0];
    const float* h0     = (const float*)d_in[1];
    const float* c0     = (const float*)d_in[2];
    const float* x0     = (const float*)d_in[3];
    const float* W_attn = (const float*)d_in[4];
    const float* b_attn = (const float*)d_in[5];
    const float* W_comb = (const float*)d_in[6];
    const float* b_comb = (const float*)d_in[7];
    const float* W_ih   = (const float*)d_in[8];
    const float* b_ih   = (const float*)d_in[9];
    const float* W_hh   = (const float*)d_in[10];
    const float* b_hh   = (const float*)d_in[11];
    const float* W_out  = (const float*)d_in[12];
    const float* b_out  = (const float*)d_in[13];
    float* out = (float*)d_out;

    float *p_logits, *p_attn, *p_lstm_in, *p_gates, *p_hnew, *p_word;
    cudaGetSymbolAddress((void**)&p_logits,  g_logits);
    cudaGetSymbolAddress((void**)&p_attn,    g_attn_applied);
    cudaGetSymbolAddress((void**)&p_lstm_in, g_lstm_in);
    cudaGetSymbolAddress((void**)&p_gates,   g_gates);
    cudaGetSymbolAddress((void**)&p_hnew,    g_hnew);
    cudaGetSymbolAddress((void**)&p_word,    g_word);

    const int TPB = 256;                  // 8 warps/block

    // 1) attn_logits = [h,x] @ W_attn^T + b_attn     (rows=L, 128 MB)
    matvec2_kernel<<<LD / 8, TPB>>>(W_attn, 2 * HD, h0, HD,
                                    W_attn + HD, 2 * HD, x0, HD,
                                    b_attn, nullptr, p_logits, LD);
    // 2) lse over L; zero attn_applied
    attn_lse_kernel<<<1, 1024>>>();
    // 3) attn_applied = (logits - lse) @ enc         (64 MB)
    attn_applied_kernel<<<dim3(HD / TPB, 32), TPB>>>(enc);
    // 4) lstm_in = [x, attn_applied] @ W_comb^T + b  (rows=H, 128 MB)
    matvec2_kernel<<<HD / 8, TPB>>>(W_comb, 2 * HD, x0, HD,
                                    W_comb + HD, 2 * HD, p_attn, HD,
                                    b_comb, nullptr, p_lstm_in, HD);
    // 5) gates = W_ih@lstm_in + W_hh@h + biases      (rows=4H, 512 MB)
    matvec2_kernel<<<(4 * HD) / 8, TPB>>>(W_ih, HD, p_lstm_in, HD,
                                          W_hh, HD, h0, HD,
                                          b_ih, b_hh, p_gates, 4 * HD);
    // 6) LSTM cell
    lstm_kernel<<<HD / TPB, TPB>>>(c0);
    // 7) word = h_new @ W_out^T + b_out              (rows=V, 2.1 GB)
    matvec2_kernel<<<VD / 8, TPB>>>(W_out, HD, p_hnew, HD,
                                    nullptr, 0, nullptr, 0,
                                    b_out, nullptr, p_word, VD);
    // 8) logsumexp over V (two stages)
    word_lse_partial_kernel<<<VD / TPB, TPB>>>();
    word_lse_final_kernel<<<1, 512>>>(VD / TPB);
    // 9) out = word - lse
    final_kernel<<<VD / TPB, TPB>>>(out);
}